// round 13
// baseline (speedup 1.0000x reference)
#include <cuda_runtime.h>

#define C_   16
#define GX_  36
#define GY_  36
#define RF_  24
#define IMG_ 64
#define G_   (GX_ * GY_)        // 1296
#define GAMMA_E 0.9f
#define GAMMA_I 0.9f
#define HALVES_ 2
#define NPART_ (C_ * HALVES_)   // 32 partials per ij
#define HF4_   162              // float4s per lateral half-row (324/2)
#define AF4H_  72               // float4s per afferent half (144/2)

// Partial per (ij, c, half). Layout [ij][32]: one 128B span per ij.
__device__ float g_part[G_ * NPART_];

__global__ __launch_bounds__(128, 16)
void cortex_partial(const float* __restrict__ x,
                    const float* __restrict__ prev,
                    const float* __restrict__ aw,
                    const float* __restrict__ ew,
                    const float* __restrict__ iw,
                    const int*   __restrict__ rx,
                    const int*   __restrict__ ry)
{
    const int ij   = blockIdx.x;          // 0..1295
    const int cy   = blockIdx.y;          // 0..31
    const int c    = cy >> 1;
    const int half = cy & 1;
    const int i  = ij / GY_;
    const int j  = ij - i * GY_;
    const int t  = threadIdx.x;

    // ---- Lateral half-row sums (162 float4 per tensor) ----
    const size_t rowbase = (size_t)(c * G_ + ij) * G_;
    const float4* e4 = reinterpret_cast<const float4*>(ew + rowbase) + half * HF4_;
    const float4* i4 = reinterpret_cast<const float4*>(iw + rowbase) + half * HF4_;

    // Explicit 2-deep batching: iter0 unconditional, iter1 predicated (t<34).
    const bool p2 = (t + 128) < HF4_;
    const float4 ve0 = __ldcs(e4 + t);
    const float4 vi0 = __ldcs(i4 + t);
    float4 ve1 = make_float4(0.f, 0.f, 0.f, 0.f);
    float4 vi1 = make_float4(0.f, 0.f, 0.f, 0.f);
    if (p2) { ve1 = __ldcs(e4 + t + 128); vi1 = __ldcs(i4 + t + 128); }

    // ---- Afferent half (72 float4; threads 0..71 active) ----
    const bool pa = t < AF4H_;
    const int rxi = __ldg(rx + i), ryj = __ldg(ry + j);
    const float4* a4 = reinterpret_cast<const float4*>(
        aw + (size_t)(c * G_ + ij) * (RF_ * RF_)) + half * AF4H_;
    float aff = 0.f;
    if (pa) {
        const float4 w4 = __ldcs(a4 + t);
        const int uv = (half * AF4H_ + t) * 4;
        const int u  = uv / RF_;
        const int v  = uv - u * RF_;
        const float* xr = x + c * IMG_ * IMG_ + (rxi + u) * IMG_ + (ryj + v);
        aff = w4.x * __ldg(xr + 0) + w4.y * __ldg(xr + 1)
            + w4.z * __ldg(xr + 2) + w4.w * __ldg(xr + 3);
    }

    float se = ((ve0.x + ve0.y) + (ve0.z + ve0.w))
             + ((ve1.x + ve1.y) + (ve1.z + ve1.w));
    float si = ((vi0.x + vi0.y) + (vi0.z + vi0.w))
             + ((vi1.x + vi1.y) + (vi1.z + vi1.w));

    // ---- Block reduce (128 threads = 4 warps) ----
    const unsigned FULL = 0xFFFFFFFFu;
    #pragma unroll
    for (int off = 16; off > 0; off >>= 1) {
        aff += __shfl_down_sync(FULL, aff, off);
        se  += __shfl_down_sync(FULL, se,  off);
        si  += __shfl_down_sync(FULL, si,  off);
    }
    __shared__ float s_red[3][4];
    const int wid = t >> 5, lid = t & 31;
    if (lid == 0) { s_red[0][wid] = aff; s_red[1][wid] = se; s_red[2][wid] = si; }
    __syncthreads();

    if (t == 0) {
        const float a = s_red[0][0] + s_red[0][1] + s_red[0][2] + s_red[0][3];
        const float e = s_red[1][0] + s_red[1][1] + s_red[1][2] + s_red[1][3];
        const float v = s_red[2][0] + s_red[2][1] + s_red[2][2] + s_red[2][3];
        const float p = __ldg(prev + c * G_ + ij);
        g_part[ij * NPART_ + cy] = a + GAMMA_E * (p * e) - GAMMA_I * (p * v);
    }

    // Allow the dependent (finalize) grid to start (R6-proven placement).
    asm volatile("griddepcontrol.launch_dependents;");
}

// One warp per ij: perfectly coalesced 128B load of the 32 partials,
// 5-step shuffle reduce, relu, broadcast-store to the 16 output channels.
__global__ __launch_bounds__(256)
void cortex_finalize(float* __restrict__ out)
{
    const int gw   = (blockIdx.x * blockDim.x + threadIdx.x) >> 5;  // warp id
    const int lane = threadIdx.x & 31;

    // Wait until all memory from cortex_partial is visible.
    asm volatile("griddepcontrol.wait;" ::: "memory");

    if (gw >= G_) return;

    float v = g_part[gw * NPART_ + lane];
    const unsigned FULL = 0xFFFFFFFFu;
    v += __shfl_down_sync(FULL, v, 16);
    v += __shfl_down_sync(FULL, v, 8);
    v += __shfl_down_sync(FULL, v, 4);
    v += __shfl_down_sync(FULL, v, 2);
    v += __shfl_down_sync(FULL, v, 1);
    const float act = fmaxf(__shfl_sync(FULL, v, 0), 0.f);
    if (lane < C_)
        out[lane * G_ + gw] = act;
}

extern "C" void kernel_launch(void* const* d_in, const int* in_sizes, int n_in,
                              void* d_out, int out_size)
{
    const float* x    = (const float*)d_in[0];
    const float* prev = (const float*)d_in[1];
    const float* aw   = (const float*)d_in[2];
    const float* ew   = (const float*)d_in[3];
    const float* iw   = (const float*)d_in[4];
    const int*   rx   = (const int*)d_in[5];
    const int*   ry   = (const int*)d_in[6];
    float* out = (float*)d_out;

    dim3 grid(G_, NPART_);
    cortex_partial<<<grid, 128>>>(x, prev, aw, ew, iw, rx, ry);

    // Finalize with PDL (overlaps the partial's tail). 162 CTAs, warp per ij.
    const int warps_per_cta = 256 / 32;
    const int n_cta = (G_ + warps_per_cta - 1) / warps_per_cta;   // 162

    cudaLaunchConfig_t cfg = {};
    cfg.gridDim  = dim3(n_cta, 1, 1);
    cfg.blockDim = dim3(256, 1, 1);
    cfg.dynamicSmemBytes = 0;
    cudaLaunchAttribute attrs[1];
    attrs[0].id = cudaLaunchAttributeProgrammaticStreamSerialization;
    attrs[0].val.programmaticStreamSerializationAllowed = 1;
    cfg.attrs = attrs;
    cfg.numAttrs = 1;
    cudaLaunchKernelEx(&cfg, cortex_finalize, out);
}

// round 14
// speedup vs baseline: 1.1320x; 1.1320x over previous
#include <cuda_runtime.h>

#define C_   16
#define GX_  36
#define GY_  36
#define RF_  24
#define IMG_ 64
#define G_   (GX_ * GY_)        // 1296
#define GAMMA_E 0.9f
#define GAMMA_I 0.9f

// Combined partial per (ij,c): aff + ge*p*exc - gi*p*inh. Written once each.
// Layout [ij][c]: each ij's 16 partials are one contiguous 64B span.
__device__ float    g_part[G_ * C_];
__device__ unsigned g_cnt[G_];      // zero-init; consuming thread resets per replay

__global__ __launch_bounds__(128, 16)
void cortex_partial(const float* __restrict__ x,
                    const float* __restrict__ prev,
                    const float* __restrict__ aw,
                    const float* __restrict__ ew,
                    const float* __restrict__ iw,
                    const int*   __restrict__ rx,
                    const int*   __restrict__ ry)
{
    const int ij = blockIdx.x;           // 0..1295
    const int c  = blockIdx.y;           // 0..15
    const int i  = ij / GY_;
    const int j  = ij - i * GY_;
    const int t  = threadIdx.x;

    // ---- Lateral row sums (324 float4 per tensor, streamed once) ----
    const size_t rowbase = (size_t)(c * G_ + ij) * G_;
    const float4* e4 = reinterpret_cast<const float4*>(ew + rowbase);
    const float4* i4 = reinterpret_cast<const float4*>(iw + rowbase);
    float se = 0.f, si = 0.f;
    const int NF4 = G_ / 4;              // 324
    #pragma unroll
    for (int o = t; o < NF4; o += 128) {
        const float4 ve = __ldcs(e4 + o);
        const float4 vi = __ldcs(i4 + o);
        se += (ve.x + ve.y) + (ve.z + ve.w);
        si += (vi.x + vi.y) + (vi.z + vi.w);
    }

    // ---- Afferent (144 float4, streamed once; x is L1/L2-resident) ----
    float aff = 0.f;
    const int rxi = __ldg(rx + i), ryj = __ldg(ry + j);
    const float4* a4 = reinterpret_cast<const float4*>(
        aw + (size_t)(c * G_ + ij) * (RF_ * RF_));
    #pragma unroll
    for (int o = t; o < (RF_ * RF_) / 4; o += 128) {
        const float4 w4 = __ldcs(a4 + o);
        const int uv = o * 4;
        const int u  = uv / RF_;
        const int v  = uv - u * RF_;
        const float* xr = x + c * IMG_ * IMG_ + (rxi + u) * IMG_ + (ryj + v);
        aff += w4.x * __ldg(xr + 0) + w4.y * __ldg(xr + 1)
             + w4.z * __ldg(xr + 2) + w4.w * __ldg(xr + 3);
    }

    // ---- Block reduce (128 threads = 4 warps) ----
    const unsigned FULL = 0xFFFFFFFFu;
    #pragma unroll
    for (int off = 16; off > 0; off >>= 1) {
        aff += __shfl_down_sync(FULL, aff, off);
        se  += __shfl_down_sync(FULL, se,  off);
        si  += __shfl_down_sync(FULL, si,  off);
    }
    __shared__ float s_red[3][4];
    const int wid = t >> 5, lid = t & 31;
    if (lid == 0) { s_red[0][wid] = aff; s_red[1][wid] = se; s_red[2][wid] = si; }
    __syncthreads();

    if (t == 0) {
        const float a = s_red[0][0] + s_red[0][1] + s_red[0][2] + s_red[0][3];
        const float e = s_red[1][0] + s_red[1][1] + s_red[1][2] + s_red[1][3];
        const float v = s_red[2][0] + s_red[2][1] + s_red[2][2] + s_red[2][3];
        const float p = __ldg(prev + c * G_ + ij);
        g_part[ij * C_ + c] = a + GAMMA_E * (p * e) - GAMMA_I * (p * v);
        // Fire-and-forget release increment: publishes this ij partial.
        asm volatile("red.release.gpu.global.add.u32 [%0], 1;"
                     :: "l"(&g_cnt[ij]) : "memory");
    }

    // Flag at CTA END (R6's measured-best placement): dependents launch only
    // when the last wave is finishing -> no mid-kernel displacement or spin.
    asm volatile("griddepcontrol.launch_dependents;");
}

// One THREAD per ij, 6 CTAs. NO griddepcontrol.wait: per-ij acquire poll on
// the counter skips the grid-wide drain that wait would impose. Launches at
// primary tail (flag at CTA end), so spins are short and non-polluting.
__global__ __launch_bounds__(256)
void cortex_finalize(float* __restrict__ out)
{
    const int ij = blockIdx.x * blockDim.x + threadIdx.x;
    if (ij >= G_) return;

    unsigned cnt;
    for (;;) {
        asm volatile("ld.acquire.gpu.global.u32 %0, [%1];"
                     : "=r"(cnt) : "l"(&g_cnt[ij]) : "memory");
        if (cnt >= C_) break;
        __nanosleep(64);
    }
    g_cnt[ij] = 0;                       // reset for next graph replay

    const float4* p4 = reinterpret_cast<const float4*>(&g_part[ij * C_]);
    const float4 a  = __ldcg(p4 + 0);
    const float4 b  = __ldcg(p4 + 1);
    const float4 cc = __ldcg(p4 + 2);
    const float4 d  = __ldcg(p4 + 3);
    const float tot = ((a.x + a.y) + (a.z + a.w))
                    + ((b.x + b.y) + (b.z + b.w))
                    + ((cc.x + cc.y) + (cc.z + cc.w))
                    + ((d.x + d.y) + (d.z + d.w));
    const float act = fmaxf(tot, 0.f);
    #pragma unroll
    for (int c = 0; c < C_; c++)
        out[c * G_ + ij] = act;
}

extern "C" void kernel_launch(void* const* d_in, const int* in_sizes, int n_in,
                              void* d_out, int out_size)
{
    const float* x    = (const float*)d_in[0];
    const float* prev = (const float*)d_in[1];
    const float* aw   = (const float*)d_in[2];
    const float* ew   = (const float*)d_in[3];
    const float* iw   = (const float*)d_in[4];
    const int*   rx   = (const int*)d_in[5];
    const int*   ry   = (const int*)d_in[6];
    float* out = (float*)d_out;

    dim3 grid(G_, C_);
    cortex_partial<<<grid, 128>>>(x, prev, aw, ew, iw, rx, ry);

    // Finalize: 6 CTAs, thread per ij, PDL + per-ij counter handoff.
    const int n_cta = (G_ + 255) / 256;   // 6

    cudaLaunchConfig_t cfg = {};
    cfg.gridDim  = dim3(n_cta, 1, 1);
    cfg.blockDim = dim3(256, 1, 1);
    cfg.dynamicSmemBytes = 0;
    cudaLaunchAttribute attrs[1];
    attrs[0].id = cudaLaunchAttributeProgrammaticStreamSerialization;
    attrs[0].val.programmaticStreamSerializationAllowed = 1;
    cfg.attrs = attrs;
    cfg.numAttrs = 1;
    cudaLaunchKernelEx(&cfg, cortex_finalize, out);
}

// round 15
// speedup vs baseline: 1.1919x; 1.0529x over previous
#include <cuda_runtime.h>

#define C_   16
#define GX_  36
#define GY_  36
#define RF_  24
#define IMG_ 64
#define G_   (GX_ * GY_)        // 1296
#define GAMMA_E 0.9f
#define GAMMA_I 0.9f

// Combined partial per (ij,c): aff + ge*p*exc - gi*p*inh.
// Layout [ij][c]: each ij's 16 partials are one contiguous 64B span.
__device__ float g_part[G_ * C_];

__global__ __launch_bounds__(128, 16)
void cortex_partial(const float* __restrict__ x,
                    const float* __restrict__ prev,
                    const float* __restrict__ aw,
                    const float* __restrict__ ew,
                    const float* __restrict__ iw,
                    const int*   __restrict__ rx,
                    const int*   __restrict__ ry)
{
    const int ij = blockIdx.x;           // 0..1295
    const int c  = blockIdx.y;           // 0..15
    const int i  = ij / GY_;
    const int j  = ij - i * GY_;
    const int t  = threadIdx.x;

    // ---- Afferent FIRST (longest dependent chain: rx/ry -> addr -> x) ----
    // Issuing it up front lets its latency hide under the lateral stream.
    float aff = 0.f;
    const int rxi = __ldg(rx + i), ryj = __ldg(ry + j);
    const float4* a4 = reinterpret_cast<const float4*>(
        aw + (size_t)(c * G_ + ij) * (RF_ * RF_));
    #pragma unroll
    for (int o = t; o < (RF_ * RF_) / 4; o += 128) {   // 144 f4: 1-2 iters
        const float4 w4 = __ldcs(a4 + o);
        const int uv = o * 4;
        const int u  = uv / RF_;
        const int v  = uv - u * RF_;
        const float* xr = x + c * IMG_ * IMG_ + (rxi + u) * IMG_ + (ryj + v);
        aff += w4.x * __ldg(xr + 0) + w4.y * __ldg(xr + 1)
             + w4.z * __ldg(xr + 2) + w4.w * __ldg(xr + 3);
    }

    // ---- Lateral row sums (324 float4 per tensor, streamed once) ----
    const size_t rowbase = (size_t)(c * G_ + ij) * G_;
    const float4* e4 = reinterpret_cast<const float4*>(ew + rowbase);
    const float4* i4 = reinterpret_cast<const float4*>(iw + rowbase);
    float se = 0.f, si = 0.f;
    const int NF4 = G_ / 4;              // 324
    #pragma unroll
    for (int o = t; o < NF4; o += 128) {
        const float4 ve = __ldcs(e4 + o);
        const float4 vi = __ldcs(i4 + o);
        se += (ve.x + ve.y) + (ve.z + ve.w);
        si += (vi.x + vi.y) + (vi.z + vi.w);
    }

    // ---- Block reduce (128 threads = 4 warps) ----
    const unsigned FULL = 0xFFFFFFFFu;
    #pragma unroll
    for (int off = 16; off > 0; off >>= 1) {
        aff += __shfl_down_sync(FULL, aff, off);
        se  += __shfl_down_sync(FULL, se,  off);
        si  += __shfl_down_sync(FULL, si,  off);
    }
    __shared__ float s_red[3][4];
    const int wid = t >> 5, lid = t & 31;
    if (lid == 0) { s_red[0][wid] = aff; s_red[1][wid] = se; s_red[2][wid] = si; }
    __syncthreads();

    if (t == 0) {
        const float a = s_red[0][0] + s_red[0][1] + s_red[0][2] + s_red[0][3];
        const float e = s_red[1][0] + s_red[1][1] + s_red[1][2] + s_red[1][3];
        const float v = s_red[2][0] + s_red[2][1] + s_red[2][2] + s_red[2][3];
        const float p = __ldg(prev + c * G_ + ij);
        g_part[ij * C_ + c] = a + GAMMA_E * (p * e) - GAMMA_I * (p * v);
    }

    // Allow the dependent (finalize) grid to start (R6-proven placement).
    asm volatile("griddepcontrol.launch_dependents;");
}

// One warp per ij: coalesced 64B load of the 16 partials, shuffle reduce,
// relu, broadcast-store to the 16 output channels (R6's proven finalize).
__global__ __launch_bounds__(256)
void cortex_finalize(float* __restrict__ out)
{
    const int gw   = (blockIdx.x * blockDim.x + threadIdx.x) >> 5;  // warp id
    const int lane = threadIdx.x & 31;

    // Wait until all memory from cortex_partial is visible.
    asm volatile("griddepcontrol.wait;" ::: "memory");

    if (gw >= G_) return;

    float v = (lane < C_) ? g_part[gw * C_ + lane] : 0.f;
    const unsigned FULL = 0xFFFFFFFFu;
    v += __shfl_down_sync(FULL, v, 8);
    v += __shfl_down_sync(FULL, v, 4);
    v += __shfl_down_sync(FULL, v, 2);
    v += __shfl_down_sync(FULL, v, 1);
    const float act = fmaxf(__shfl_sync(FULL, v, 0), 0.f);
    if (lane < C_)
        out[lane * G_ + gw] = act;
}

extern "C" void kernel_launch(void* const* d_in, const int* in_sizes, int n_in,
                              void* d_out, int out_size)
{
    const float* x    = (const float*)d_in[0];
    const float* prev = (const float*)d_in[1];
    const float* aw   = (const float*)d_in[2];
    const float* ew   = (const float*)d_in[3];
    const float* iw   = (const float*)d_in[4];
    const int*   rx   = (const int*)d_in[5];
    const int*   ry   = (const int*)d_in[6];
    float* out = (float*)d_out;

    dim3 grid(G_, C_);
    cortex_partial<<<grid, 128>>>(x, prev, aw, ew, iw, rx, ry);

    // Finalize with PDL (overlaps the partial's tail). 162 CTAs, warp per ij.
    const int warps_per_cta = 256 / 32;
    const int n_cta = (G_ + warps_per_cta - 1) / warps_per_cta;   // 162

    cudaLaunchConfig_t cfg = {};
    cfg.gridDim  = dim3(n_cta, 1, 1);
    cfg.blockDim = dim3(256, 1, 1);
    cfg.dynamicSmemBytes = 0;
    cudaLaunchAttribute attrs[1];
    attrs[0].id = cudaLaunchAttributeProgrammaticStreamSerialization;
    attrs[0].val.programmaticStreamSerializationAllowed = 1;
    cfg.attrs = attrs;
    cfg.numAttrs = 1;
    cudaLaunchKernelEx(&cfg, cortex_finalize, out);
}